// round 6
// baseline (speedup 1.0000x reference)
#include <cuda_runtime.h>

// ValueLayerSlow: Pauli expectations, 16 strings, 10 qubits, real states.
//   Z ops (op o -> d-bit 9-o): sum_d (-1)^{bit} x_d^2
//   X ops (10,11,12 -> masks 512/256/128): 2 * sum_{pairs} x_d x_{d^m}
//   Y ops (13,14,15): exactly 0.
//
// R6: TWO warps per state (64-thread block per state) to double occupancy
// (4096 -> 8192 warps; grid-limited occ 38% -> ~80%). Element d = i*128 +
// lane*4 + j. Warp 0 holds i in {0,1,4,5}, warp 1 holds i in {2,3,6,7}:
//   - masks 512 & 128 are register-local in each warp
//   - mask 256 pairs (0,2)(1,3)(4,6)(5,7): w0 exports v4,v5 / w1 exports
//     v2,v3 via smem; each warp computes 2 of the 4 cross pairs
//   - per-lane S exchanged via smem so the Walsh-Hadamard (lane-bit Z ops)
//     runs on the combined S with no second sync.

#define DOT4(a, b) ((a).x*(b).x + (a).y*(b).y + (a).z*(b).z + (a).w*(b).w)

__global__ void __launch_bounds__(64)
pauli_expect_kernel(const float* __restrict__ x, float* __restrict__ out,
                    int n_states) {
    __shared__ float4 xch[2][32][2];  // exported vector pairs per warp/lane
    __shared__ float  sS[2][32];      // per-lane S per warp
    __shared__ float  red[2][8];      // butterfly-reduced scalars per warp

    const int tid  = threadIdx.x;
    const int wid  = tid >> 5;
    const int lane = tid & 31;
    const int state = blockIdx.x;
    if (state >= n_states) return;

    const float4* xp = reinterpret_cast<const float4*>(x) + (size_t)state * 256;
    const int i0 = wid ? 2 : 0;   // w0: i=0,1,4,5 ; w1: i=2,3,6,7

    float4 va = __ldcs(&xp[(i0 + 0) * 32 + lane]);
    float4 vb = __ldcs(&xp[(i0 + 1) * 32 + lane]);
    float4 vc = __ldcs(&xp[(i0 + 4) * 32 + lane]);
    float4 vd = __ldcs(&xp[(i0 + 5) * 32 + lane]);

    // export the vectors the other warp needs for mask-256:
    // w0 exports v4,v5 ; w1 exports v2,v3
    xch[wid][lane][0] = wid ? va : vc;
    xch[wid][lane][1] = wid ? vb : vd;

    // ---- squares ----
    float z1p = 0.f, z0p = 0.f;
    float sa, sb, sc, sd;
#define SQ(v, s) { float a0=(v).x*(v).x, a1=(v).y*(v).y, a2=(v).z*(v).z, a3=(v).w*(v).w; \
                   float p01=a0+a1, p23=a2+a3; (s)=p01+p23; \
                   z1p += p01 - p23; z0p += (a0-a1) + (a2-a3); }
    SQ(va, sa) SQ(vb, sb) SQ(vc, sc) SQ(vd, sd)
#undef SQ

    float Sw  = (sa + sb) + (sc + sd);
    float z9p = (sa + sb) - (sc + sd);   // d-bit9 sign (i bit2)
    float z7p = (sa - sb) + (sc - sd);   // d-bit7 sign (i bit0)
    float z8p = wid ? -Sw : Sw;          // d-bit8 sign: +{0,1,4,5} -{2,3,6,7}
    sS[wid][lane] = Sw;

    // ---- register-local X dots ----
    float x9p = DOT4(va, vc) + DOT4(vb, vd);  // w0:(0,4)+(1,5) w1:(2,6)+(3,7)
    float x7p = DOT4(va, vb) + DOT4(vc, vd);  // w0:(0,1)+(4,5) w1:(2,3)+(6,7)

    __syncthreads();

    // ---- cross-warp X (mask 256) + combined S ----
    float4 pa = xch[1 - wid][lane][0];
    float4 pb = xch[1 - wid][lane][1];
    // w0: pa=v2,pb=v3 -> (0,2)+(1,3) ; w1: pa=v4,pb=v5 -> (4,6)+(5,7)
    float x8p = wid ? (DOT4(pa, vc) + DOT4(pb, vd))
                    : (DOT4(va, pa) + DOT4(vb, pb));
    float Scomb = Sw + sS[1 - wid][lane];

    // ---- 8-var interleaved butterfly allreduce (per warp) ----
    const unsigned FULL = 0xFFFFFFFFu;
#pragma unroll
    for (int o = 16; o > 0; o >>= 1) {
        z9p += __shfl_xor_sync(FULL, z9p, o);
        z8p += __shfl_xor_sync(FULL, z8p, o);
        z7p += __shfl_xor_sync(FULL, z7p, o);
        z1p += __shfl_xor_sync(FULL, z1p, o);
        z0p += __shfl_xor_sync(FULL, z0p, o);
        x9p += __shfl_xor_sync(FULL, x9p, o);
        x8p += __shfl_xor_sync(FULL, x8p, o);
        x7p += __shfl_xor_sync(FULL, x7p, o);
    }

    // ---- Walsh-Hadamard over combined S (final, no cross-warp combine) ----
    // lane 2^k holds Z on d-bit (k+2) = op (7-k)
    float w = Scomb;
#pragma unroll
    for (int k = 0; k < 5; k++) {
        float p = __shfl_xor_sync(FULL, w, 1 << k);
        w = (lane & (1 << k)) ? (p - w) : (p + w);
    }

    // publish this warp's 8 reduced scalars (all lanes hold totals)
    if (lane < 8) {
        float r = (lane < 4)
            ? (lane == 0 ? z9p : lane == 1 ? z8p : lane == 2 ? z7p : z1p)
            : (lane == 4 ? z0p : lane == 5 ? x9p : lane == 6 ? x8p : x7p);
        red[wid][lane] = r;
    }
    __syncthreads();

    if (wid == 0) {
        // move WH results to output lanes: o3..o7 <- lanes 16,8,4,2,1
        int src = (1 << (7 - lane)) & 31;
        float wmv = __shfl_sync(FULL, w, src);

        if (lane < 16) {
            // this warp's scalar for this output lane
            float A = (lane < 8)
                ? (lane == 0 ? z9p : lane == 1 ? z8p : z7p)
                : (lane == 8 ? z1p : lane == 9 ? z0p :
                   lane == 10 ? x9p : lane == 11 ? x8p : x7p);
            int idx = ((lane < 8) ? lane : (lane - 5)) & 7;
            float B = red[1][idx];   // other warp's matching scalar
            float AB = A + B;

            float val = (lane < 3)  ? AB            // ops 0,1,2 (z9,z8,z7)
                      : (lane < 8)  ? wmv           // ops 3..7 (WH)
                      : (lane < 10) ? AB            // ops 8,9 (z1,z0)
                      : (lane < 13) ? 2.0f * AB     // ops 10,11,12 (X)
                      : 0.0f;                       // ops 13,14,15 (Y)
            out[(size_t)state * 16 + lane] = val;
        }
    }
}

extern "C" void kernel_launch(void* const* d_in, const int* in_sizes, int n_in,
                              void* d_out, int out_size) {
    const float* x = (const float*)d_in[0];
    float* out = (float*)d_out;
    const int n_states = in_sizes[0] / 1024;     // 4096 for (8,512,1024)
    pauli_expect_kernel<<<n_states, 64>>>(x, out, n_states);
}

// round 7
// speedup vs baseline: 1.4241x; 1.4241x over previous
#include <cuda_runtime.h>

// ValueLayerSlow: Pauli expectation values <psi|O|psi> for 16 Pauli strings on
// 10 qubits (dim=1024), states are REAL vectors (8*512 = 4096 states).
//
// Algebraic reduction (states real):
//   Z on bit b (ops 0..9, op o -> bit 9-o):  sum_d (-1)^{bit_b(d)} x_d^2
//   X on bit b (ops 10,11,12 -> masks 512/256/128): 2*sum_{pairs} x_d x_{d^m}
//   Y ops (13,14,15): exactly 0.
//
// One warp per state. Lane t holds d = i*128 + t*4 + j (8 x float4).
// R7 (from R4, the measured-fastest structure):
//   - loads split 4+4 with squares between (MLP_p1 8->4: lower cross-CTA
//     L1tex-queue spread in the single wave)
//   - butterfly all-reduce leaves totals in every lane, so output is ONE
//     coalesced STG.32 across lanes 0..15 (replaces 16 predicated stores)

__global__ void __launch_bounds__(128)
pauli_expect_kernel(const float* __restrict__ x, float* __restrict__ out,
                    int n_states) {
    const int warp = (blockIdx.x * blockDim.x + threadIdx.x) >> 5;
    const int lane = threadIdx.x & 31;
    if (warp >= n_states) return;

    const float4* xp = reinterpret_cast<const float4*>(x) + (size_t)warp * 256;

    float4 v[8];
    float s[8];
    float z1 = 0.f;  // op8: Z on bit1 (sign from j>>1)
    float z0 = 0.f;  // op9: Z on bit0 (sign from j&1)

#define SQ(i) { float a0 = v[i].x * v[i].x, a1 = v[i].y * v[i].y;          \
                float a2 = v[i].z * v[i].z, a3 = v[i].w * v[i].w;          \
                float p01 = a0 + a1, p23 = a2 + a3;                        \
                s[i] = p01 + p23;                                          \
                z1 += p01 - p23; z0 += (a0 - a1) + (a2 - a3); }

    // ---- batch 1: loads + squares ----
#pragma unroll
    for (int i = 0; i < 4; i++) v[i] = __ldcs(&xp[i * 32 + lane]);
    SQ(0) SQ(1) SQ(2) SQ(3)

    // compiler fence: keep batch-2 loads behind batch-1 compute in PTX order
    asm volatile("" ::: "memory");

    // ---- batch 2: loads + squares ----
#pragma unroll
    for (int i = 4; i < 8; i++) v[i] = __ldcs(&xp[i * 32 + lane]);
    SQ(4) SQ(5) SQ(6) SQ(7)
#undef SQ

    float e01 = s[0] + s[1], e23 = s[2] + s[3];
    float e45 = s[4] + s[5], e67 = s[6] + s[7];
    float S  = (e01 + e23) + (e45 + e67);          // total sum of squares
    float z9 = (e01 + e23) - (e45 + e67);          // op0: Z bit9 (i bit2)
    float z8 = (e01 + e45) - (e23 + e67);          // op1: Z bit8 (i bit1)
    float z7 = ((s[0] + s[2]) + (s[4] + s[6]))
             - ((s[1] + s[3]) + (s[5] + s[7]));    // op2: Z bit7 (i bit0)

    // ---- X ops: register-resident pair dots (each unordered pair once)
#define DOT4(a, b) ((a).x*(b).x + (a).y*(b).y + (a).z*(b).z + (a).w*(b).w)
    float x9 = DOT4(v[0], v[4]) + DOT4(v[1], v[5])
             + DOT4(v[2], v[6]) + DOT4(v[3], v[7]);   // mask 512 (op10)
    float x8 = DOT4(v[0], v[2]) + DOT4(v[1], v[3])
             + DOT4(v[4], v[6]) + DOT4(v[5], v[7]);   // mask 256 (op11)
    float x7 = DOT4(v[0], v[1]) + DOT4(v[2], v[3])
             + DOT4(v[4], v[5]) + DOT4(v[6], v[7]);   // mask 128 (op12)
#undef DOT4

    // ---- 8 interleaved butterfly all-reduces (totals land in EVERY lane) ----
    const unsigned FULL = 0xFFFFFFFFu;
#pragma unroll
    for (int o = 16; o > 0; o >>= 1) {
        z9 += __shfl_xor_sync(FULL, z9, o);
        z8 += __shfl_xor_sync(FULL, z8, o);
        z7 += __shfl_xor_sync(FULL, z7, o);
        z1 += __shfl_xor_sync(FULL, z1, o);
        z0 += __shfl_xor_sync(FULL, z0, o);
        x9 += __shfl_xor_sync(FULL, x9, o);
        x8 += __shfl_xor_sync(FULL, x8, o);
        x7 += __shfl_xor_sync(FULL, x7, o);
    }

    // ---- Walsh-Hadamard over S: lane 2^k holds Z on d-bit (k+2) = op (7-k)
    float w = S;
#pragma unroll
    for (int k = 0; k < 5; k++) {
        float p = __shfl_xor_sync(FULL, w, 1 << k);
        w = (lane & (1 << k)) ? (p - w) : (p + w);
    }
    // route WH results to output lanes 3..7: op l <- WH lane 2^(7-l)
    int src = (lane >= 3 && lane < 8) ? (1 << (7 - lane)) : 0;
    float wmv = __shfl_sync(FULL, w, src);

    // ---- one coalesced STG.32: out[warp*16 + lane], lanes 0..15 ----
    float val = (lane < 3)  ? (lane == 0 ? z9 : lane == 1 ? z8 : z7)
              : (lane < 8)  ? wmv
              : (lane < 10) ? (lane == 8 ? z1 : z0)
              : (lane < 13) ? 2.0f * (lane == 10 ? x9 : lane == 11 ? x8 : x7)
              : 0.0f;                             // ops 13,14,15 (Y) = 0
    if (lane < 16) out[(size_t)warp * 16 + lane] = val;
}

extern "C" void kernel_launch(void* const* d_in, const int* in_sizes, int n_in,
                              void* d_out, int out_size) {
    const float* x = (const float*)d_in[0];
    float* out = (float*)d_out;
    const int n_states = in_sizes[0] / 1024;     // 4096 for (8,512,1024)
    const int blocks = (n_states + 3) / 4;       // 4 warps (128 thr) per block
    pauli_expect_kernel<<<blocks, 128>>>(x, out, n_states);
}